// round 1
// baseline (speedup 1.0000x reference)
#include <cuda_runtime.h>
#include <cuda_bf16.h>
#include <math.h>

// Problem constants
#define B_   4
#define T_   2048
#define C_   1024
#define H_   16
#define D_   64
#define M_   (B_ * T_)        // 8192 rows
#define C3_  (3 * C_)         // 3072

// Scratch (device globals — no cudaMalloc allowed)
__device__ float g_qkv[M_ * C3_];   // [8192, 3072]
__device__ float g_y[M_ * C_];      // [8192, 1024]

// ---------------------------------------------------------------------------
// SGEMM: C[M,N] = A[M,K] * B[K,N], all row-major fp32.
// 128x128 tile, BK=8, 256 threads, 8x8 per-thread microtile.
// M % 128 == 0, N % 128 == 0, K % 8 == 0 guaranteed by caller.
// ---------------------------------------------------------------------------
__global__ __launch_bounds__(256)
void sgemm_kernel(const float* __restrict__ A,
                  const float* __restrict__ Bm,
                  float* __restrict__ Cm,
                  int M, int N, int K) {
    __shared__ float As[8][128];   // transposed A tile: As[k][m]
    __shared__ float Bs[8][128];   // Bs[k][n]

    const int tid = threadIdx.x;
    const int tx = tid & 15;       // 0..15 -> n
    const int ty = tid >> 4;       // 0..15 -> m
    const int m0 = blockIdx.y * 128;
    const int n0 = blockIdx.x * 128;

    // A-load mapping: 128 rows x 8 cols = 1024 floats = 256 * float4
    const int ar = tid >> 1;              // 0..127 (row in tile)
    const int ac = (tid & 1) * 4;         // 0 or 4 (col in tile)
    // B-load mapping: 8 rows x 128 cols
    const int br = tid >> 5;              // 0..7
    const int bc = (tid & 31) * 4;        // 0..124

    float acc[8][8];
#pragma unroll
    for (int i = 0; i < 8; i++)
#pragma unroll
        for (int j = 0; j < 8; j++) acc[i][j] = 0.0f;

    for (int kt = 0; kt < K; kt += 8) {
        float4 av = *reinterpret_cast<const float4*>(A + (size_t)(m0 + ar) * K + kt + ac);
        As[ac + 0][ar] = av.x;
        As[ac + 1][ar] = av.y;
        As[ac + 2][ar] = av.z;
        As[ac + 3][ar] = av.w;
        *reinterpret_cast<float4*>(&Bs[br][bc]) =
            *reinterpret_cast<const float4*>(Bm + (size_t)(kt + br) * N + n0 + bc);
        __syncthreads();

#pragma unroll
        for (int k = 0; k < 8; k++) {
            float a[8], b[8];
            *reinterpret_cast<float4*>(a)     = *reinterpret_cast<float4*>(&As[k][ty * 8]);
            *reinterpret_cast<float4*>(a + 4) = *reinterpret_cast<float4*>(&As[k][ty * 8 + 4]);
            *reinterpret_cast<float4*>(b)     = *reinterpret_cast<float4*>(&Bs[k][tx * 8]);
            *reinterpret_cast<float4*>(b + 4) = *reinterpret_cast<float4*>(&Bs[k][tx * 8 + 4]);
#pragma unroll
            for (int i = 0; i < 8; i++)
#pragma unroll
                for (int j = 0; j < 8; j++)
                    acc[i][j] = fmaf(a[i], b[j], acc[i][j]);
        }
        __syncthreads();
    }

#pragma unroll
    for (int i = 0; i < 8; i++) {
        float* crow = Cm + (size_t)(m0 + ty * 8 + i) * N + n0 + tx * 8;
        float4 v0 = make_float4(acc[i][0], acc[i][1], acc[i][2], acc[i][3]);
        float4 v1 = make_float4(acc[i][4], acc[i][5], acc[i][6], acc[i][7]);
        *reinterpret_cast<float4*>(crow)     = v0;
        *reinterpret_cast<float4*>(crow + 4) = v1;
    }
}

// ---------------------------------------------------------------------------
// Flash attention (fp32, causal, muP scale 1/D).
// Grid: (T/64, H, B). Block: 256 threads. One CTA = one (b,h,q-tile of 64).
// qkv layout: [B*T, 3C]; Q at col h*64, K at C + h*64, V at 2C + h*64.
// Writes y in [B, T, C] layout with head h at cols h*64..h*64+63.
// Dynamic smem layout (floats):
//   Qst[64][64]  (d-major: Qst[d][q])
//   Kst[64][64]  (d-major: Kst[d][k])
//   Vs [64][64]  (k-major: Vs[k][d])
//   Ssm[64][66]  (scores / probs, padded)
//   m_s[64], l_s[64], sc_s[64]
// ---------------------------------------------------------------------------
#define SSM_LD 66
#define ATTN_SMEM_FLOATS (64*64*3 + 64*SSM_LD + 3*64)
#define ATTN_SMEM_BYTES  (ATTN_SMEM_FLOATS * 4)

__global__ __launch_bounds__(256)
void attn_kernel(const float* __restrict__ qkv, float* __restrict__ y) {
    extern __shared__ float sm[];
    float* Qst = sm;                 // [64][64]
    float* Kst = Qst + 64 * 64;      // [64][64]
    float* Vs  = Kst + 64 * 64;      // [64][64]
    float* Ssm = Vs + 64 * 64;       // [64][66]
    float* m_s  = Ssm + 64 * SSM_LD; // [64]
    float* l_s  = m_s + 64;          // [64]
    float* sc_s = l_s + 64;          // [64]

    const int tid = threadIdx.x;
    const int tx = tid & 15;   // 0..15
    const int ty = tid >> 4;   // 0..15
    const int qtile = blockIdx.x;       // 0..31
    const int h = blockIdx.y;           // 0..15
    const int b = blockIdx.z;           // 0..3
    const int q0 = qtile * 64;
    const float inv_d = 1.0f / (float)D_;

    const size_t row_base = (size_t)b * T_;
    const int hcol = h * D_;

    // Load Q tile into Qst[d][q] (d-major)
    {
#pragma unroll
        for (int it = 0; it < 4; it++) {
            int idx = it * 256 + tid;       // float4 index 0..1023
            int q = idx >> 4;               // 0..63
            int d4 = (idx & 15) * 4;        // 0..60
            float4 qv = *reinterpret_cast<const float4*>(
                qkv + (row_base + q0 + q) * C3_ + hcol + d4);
            Qst[(d4 + 0) * 64 + q] = qv.x;
            Qst[(d4 + 1) * 64 + q] = qv.y;
            Qst[(d4 + 2) * 64 + q] = qv.z;
            Qst[(d4 + 3) * 64 + q] = qv.w;
        }
    }
    if (tid < 64) {
        m_s[tid] = -INFINITY;
        l_s[tid] = 0.0f;
    }

    float o[4][4];
#pragma unroll
    for (int i = 0; i < 4; i++)
#pragma unroll
        for (int j = 0; j < 4; j++) o[i][j] = 0.0f;

    const int ntiles = qtile + 1;
    for (int kt = 0; kt < ntiles; kt++) {
        const int k0 = kt * 64;
        __syncthreads();   // protect Kst/Vs/Ssm from previous iteration readers

        // Load K (d-major) and V (k-major) tiles
#pragma unroll
        for (int it = 0; it < 4; it++) {
            int idx = it * 256 + tid;
            int kk = idx >> 4;
            int d4 = (idx & 15) * 4;
            const float* rowp = qkv + (row_base + k0 + kk) * C3_;
            float4 kv = *reinterpret_cast<const float4*>(rowp + C_ + hcol + d4);
            Kst[(d4 + 0) * 64 + kk] = kv.x;
            Kst[(d4 + 1) * 64 + kk] = kv.y;
            Kst[(d4 + 2) * 64 + kk] = kv.z;
            Kst[(d4 + 3) * 64 + kk] = kv.w;
            float4 vv = *reinterpret_cast<const float4*>(rowp + 2 * C_ + hcol + d4);
            *reinterpret_cast<float4*>(&Vs[kk * 64 + d4]) = vv;
        }
        __syncthreads();

        // S = Q * K^T  (4x4 microtile per thread)
        float acc[4][4];
#pragma unroll
        for (int i = 0; i < 4; i++)
#pragma unroll
            for (int j = 0; j < 4; j++) acc[i][j] = 0.0f;

#pragma unroll 8
        for (int d = 0; d < 64; d++) {
            float a[4], bb[4];
            *reinterpret_cast<float4*>(a)  = *reinterpret_cast<float4*>(&Qst[d * 64 + ty * 4]);
            *reinterpret_cast<float4*>(bb) = *reinterpret_cast<float4*>(&Kst[d * 64 + tx * 4]);
#pragma unroll
            for (int i = 0; i < 4; i++)
#pragma unroll
                for (int j = 0; j < 4; j++)
                    acc[i][j] = fmaf(a[i], bb[j], acc[i][j]);
        }

        const bool diag = (kt == qtile);
#pragma unroll
        for (int i = 0; i < 4; i++) {
            int qr = ty * 4 + i;
#pragma unroll
            for (int j = 0; j < 4; j++) {
                int kc = tx * 4 + j;
                float s = acc[i][j] * inv_d;
                if (diag && kc > qr) s = -1e30f;
                Ssm[qr * SSM_LD + kc] = s;
            }
        }
        __syncthreads();

        // Online softmax: one thread per query row
        if (tid < 64) {
            const int r = tid;
            float mo = m_s[r];
            float mn = mo;
#pragma unroll 8
            for (int j = 0; j < 64; j++)
                mn = fmaxf(mn, Ssm[r * SSM_LD + j]);
            float corr = __expf(mo - mn);   // 0 when mo == -inf
            float sum = 0.0f;
#pragma unroll 8
            for (int j = 0; j < 64; j++) {
                float p = __expf(Ssm[r * SSM_LD + j] - mn);
                Ssm[r * SSM_LD + j] = p;
                sum += p;
            }
            l_s[r] = l_s[r] * corr + sum;
            m_s[r] = mn;
            sc_s[r] = corr;
        }
        __syncthreads();

        // O = O*corr + P * V   (4 q-rows x 4 d-cols per thread)
        float ci[4];
#pragma unroll
        for (int i = 0; i < 4; i++) ci[i] = sc_s[ty * 4 + i];
#pragma unroll
        for (int i = 0; i < 4; i++)
#pragma unroll
            for (int j = 0; j < 4; j++) o[i][j] *= ci[i];

#pragma unroll 4
        for (int k = 0; k < 64; k++) {
            float p[4], v[4];
#pragma unroll
            for (int i = 0; i < 4; i++) p[i] = Ssm[(ty * 4 + i) * SSM_LD + k];
            *reinterpret_cast<float4*>(v) = *reinterpret_cast<float4*>(&Vs[k * 64 + tx * 4]);
#pragma unroll
            for (int i = 0; i < 4; i++)
#pragma unroll
                for (int j = 0; j < 4; j++)
                    o[i][j] = fmaf(p[i], v[j], o[i][j]);
        }
    }
    __syncthreads();

    // Normalize and write out: y[(b*T + q)*C + h*64 + d]
#pragma unroll
    for (int i = 0; i < 4; i++) {
        int qr = ty * 4 + i;
        float invl = 1.0f / l_s[qr];
        float* yrow = y + (row_base + q0 + qr) * C_ + hcol + tx * 4;
        float4 ov = make_float4(o[i][0] * invl, o[i][1] * invl,
                                o[i][2] * invl, o[i][3] * invl);
        *reinterpret_cast<float4*>(yrow) = ov;
    }
}

// ---------------------------------------------------------------------------
// Launch
// ---------------------------------------------------------------------------
extern "C" void kernel_launch(void* const* d_in, const int* in_sizes, int n_in,
                              void* d_out, int out_size) {
    const float* x      = (const float*)d_in[0];   // [4, 2048, 1024]
    const float* W_attn = (const float*)d_in[1];   // [1024, 3072]
    const float* W_proj = (const float*)d_in[2];   // [1024, 1024]
    float* out = (float*)d_out;                    // [4, 2048, 1024]

    float* qkv = nullptr;
    float* y = nullptr;
    cudaGetSymbolAddress((void**)&qkv, g_qkv);
    cudaGetSymbolAddress((void**)&y, g_y);

    cudaFuncSetAttribute(attn_kernel,
                         cudaFuncAttributeMaxDynamicSharedMemorySize,
                         ATTN_SMEM_BYTES);

    // 1) qkv = x @ W_attn   [8192,1024]x[1024,3072]
    sgemm_kernel<<<dim3(C3_ / 128, M_ / 128), 256>>>(x, W_attn, qkv, M_, C3_, C_);

    // 2) causal attention -> y [8192,1024]
    attn_kernel<<<dim3(T_ / 64, H_, B_), 256, ATTN_SMEM_BYTES>>>(qkv, y);

    // 3) out = y @ W_proj   [8192,1024]x[1024,1024]
    sgemm_kernel<<<dim3(C_ / 128, M_ / 128), 256>>>(y, W_proj, out, M_, C_, C_);
}

// round 3
// speedup vs baseline: 1.6229x; 1.6229x over previous
#include <cuda_runtime.h>
#include <cuda_bf16.h>
#include <math.h>

// Problem constants
#define B_   4
#define T_   2048
#define C_   1024
#define H_   16
#define D_   64
#define M_   (B_ * T_)        // 8192
#define C3_  (3 * C_)         // 3072

// ---------------------------------------------------------------------------
// Device scratch (no cudaMalloc allowed)
// ---------------------------------------------------------------------------
__device__ __align__(1024) float g_qkv[M_ * C3_];   // [8192,3072]
__device__ __align__(1024) float g_y[M_ * C_];      // [8192,1024]

// ---------------------------------------------------------------------------
// Helpers
// ---------------------------------------------------------------------------
__device__ __forceinline__ unsigned smem_to_u32(const void* p) {
    unsigned a;
    asm("{ .reg .u64 t; cvta.to.shared.u64 t, %1; cvt.u32.u64 %0, t; }"
        : "=r"(a) : "l"(p));
    return a;
}

#define CP_ASYNC16(dst, src) \
    asm volatile("cp.async.cg.shared.global [%0], [%1], 16;" \
                 :: "r"(dst), "l"(src) : "memory")

__device__ __forceinline__ unsigned f2tf32(float x) {
    unsigned r;
    asm("cvt.rna.tf32.f32 %0, %1;" : "=r"(r) : "f"(x));
    return r;
}

__device__ __forceinline__ void mma_tf32(float* c, const unsigned* a,
                                         const unsigned* b) {
    asm volatile(
        "mma.sync.aligned.m16n8k8.row.col.f32.tf32.tf32.f32 "
        "{%0,%1,%2,%3}, {%4,%5,%6,%7}, {%8,%9}, {%0,%1,%2,%3};"
        : "+f"(c[0]), "+f"(c[1]), "+f"(c[2]), "+f"(c[3])
        : "r"(a[0]), "r"(a[1]), "r"(a[2]), "r"(a[3]),
          "r"(b[0]), "r"(b[1]));
}

// ---------------------------------------------------------------------------
// tf32 tensor-core GEMM: C[M,N] = A[M,K] * B[K,N], all row-major fp32.
// CTA tile 128x128, BK=32, 128 threads (4 warps, 2x2 grid, warp tile 64x64),
// 3-stage cp.async pipeline. M%128==0, N%128==0, K%32==0.
// ---------------------------------------------------------------------------
#define BM 128
#define BN 128
#define BK 32
#define GSTAGES 3
#define A_LDW 36                      // fp32 words per A smem row (pad: banks 4g+t)
#define B_LDW 136                     // fp32 words per B smem k-row (banks 8t+g)
#define A_STAGE_W (BM * A_LDW)        // 4608 words
#define B_STAGE_W (BK * B_LDW)        // 4352 words
#define STAGE_W   (A_STAGE_W + B_STAGE_W)   // 8960 words
#define GSMEM_BYTES (GSTAGES * STAGE_W * 4) // 107520 B -> 2 CTAs/SM

__global__ void __launch_bounds__(128, 2)
gemm_tf32_kernel(const float* __restrict__ A, const float* __restrict__ Bm,
                 float* __restrict__ Cm, int M, int N, int K) {
    extern __shared__ __align__(16) float sm[];
    const unsigned sbase = smem_to_u32(sm);

    const int tid = threadIdx.x;
    const int wid = tid >> 5;
    const int lane = tid & 31;
    const int g = lane >> 2;          // 0..7
    const int t = lane & 3;           // 0..3
    const int warp_m = wid & 1;       // 0..1
    const int warp_n = wid >> 1;      // 0..1
    const int m0 = blockIdx.y * BM;
    const int n0 = blockIdx.x * BN;
    const int nchunks = K / BK;

    float acc[4][8][4];
#pragma unroll
    for (int i = 0; i < 4; i++)
#pragma unroll
        for (int j = 0; j < 8; j++)
#pragma unroll
            for (int r = 0; r < 4; r++) acc[i][j][r] = 0.0f;

    // cp.async one BK-chunk into stage slot
    auto issue = [&](int chunk) {
        const unsigned st = sbase + (unsigned)((chunk % GSTAGES) * STAGE_W * 4);
        // A tile: 128 rows x 128 B
#pragma unroll
        for (int i = 0; i < 8; i++) {
            int idx = tid + i * 128;          // 0..1023
            int row = idx >> 3;               // 0..127
            int c4 = (idx & 7) * 4;           // 0,4,...28
            const float* src = A + (size_t)(m0 + row) * K + chunk * BK + c4;
            unsigned dst = st + (unsigned)((row * A_LDW + c4) * 4);
            CP_ASYNC16(dst, src);
        }
        // B tile: 32 k-rows x 512 B
        const unsigned stb = st + (unsigned)(A_STAGE_W * 4);
#pragma unroll
        for (int i = 0; i < 8; i++) {
            int idx = tid + i * 128;
            int kr = idx >> 5;                // 0..31
            int c4 = (idx & 31) * 4;          // 0..124
            const float* src = Bm + (size_t)(chunk * BK + kr) * N + n0 + c4;
            unsigned dst = stb + (unsigned)((kr * B_LDW + c4) * 4);
            CP_ASYNC16(dst, src);
        }
        asm volatile("cp.async.commit_group;" ::: "memory");
    };

    issue(0);
    issue(1);

    for (int c = 0; c < nchunks; c++) {
        if (c < nchunks - 1)
            asm volatile("cp.async.wait_group 1;" ::: "memory");
        else
            asm volatile("cp.async.wait_group 0;" ::: "memory");
        __syncthreads();

        if (c + 2 < nchunks) issue(c + 2);

        const float* As = sm + (c % GSTAGES) * STAGE_W + warp_m * 64 * A_LDW;
        const float* Bs = sm + (c % GSTAGES) * STAGE_W + A_STAGE_W + warp_n * 64;

#pragma unroll
        for (int ks = 0; ks < 4; ks++) {
            unsigned af[4][4], bf[8][2];
#pragma unroll
            for (int mt = 0; mt < 4; mt++) {
                const float* ap = As + (mt * 16 + g) * A_LDW + ks * 8 + t;
                af[mt][0] = f2tf32(ap[0]);
                af[mt][1] = f2tf32(ap[8 * A_LDW]);
                af[mt][2] = f2tf32(ap[4]);
                af[mt][3] = f2tf32(ap[8 * A_LDW + 4]);
            }
#pragma unroll
            for (int nt = 0; nt < 8; nt++) {
                const float* bp = Bs + (ks * 8 + t) * B_LDW + nt * 8 + g;
                bf[nt][0] = f2tf32(bp[0]);
                bf[nt][1] = f2tf32(bp[4 * B_LDW]);
            }
#pragma unroll
            for (int mt = 0; mt < 4; mt++)
#pragma unroll
                for (int nt = 0; nt < 8; nt++)
                    mma_tf32(acc[mt][nt], af[mt], bf[nt]);
        }
    }

    // Epilogue: direct fp32 stores
#pragma unroll
    for (int mt = 0; mt < 4; mt++) {
        int row0 = m0 + warp_m * 64 + mt * 16 + g;
#pragma unroll
        for (int nt = 0; nt < 8; nt++) {
            int col = n0 + warp_n * 64 + nt * 8 + 2 * t;
            float2 v0 = make_float2(acc[mt][nt][0], acc[mt][nt][1]);
            float2 v1 = make_float2(acc[mt][nt][2], acc[mt][nt][3]);
            *reinterpret_cast<float2*>(Cm + (size_t)row0 * N + col) = v0;
            *reinterpret_cast<float2*>(Cm + (size_t)(row0 + 8) * N + col) = v1;
        }
    }
}

// ---------------------------------------------------------------------------
// Flash attention (fp32, causal, muP scale 1/D). Same as R1 (proven).
// ---------------------------------------------------------------------------
#define SSM_LD 66
#define ATTN_SMEM_FLOATS (64*64*3 + 64*SSM_LD + 3*64)
#define ATTN_SMEM_BYTES  (ATTN_SMEM_FLOATS * 4)

__global__ void __launch_bounds__(256)
attn_kernel(const float* __restrict__ qkv, float* __restrict__ y) {
    extern __shared__ float smf[];
    float* Qst = smf;                // [64][64] d-major
    float* Kst = Qst + 64 * 64;      // [64][64] d-major
    float* Vs  = Kst + 64 * 64;      // [64][64] k-major
    float* Ssm = Vs + 64 * 64;       // [64][66]
    float* m_s  = Ssm + 64 * SSM_LD;
    float* l_s  = m_s + 64;
    float* sc_s = l_s + 64;

    const int tid = threadIdx.x;
    const int tx = tid & 15;
    const int ty = tid >> 4;
    const int qtile = blockIdx.x;
    const int h = blockIdx.y;
    const int b = blockIdx.z;
    const int q0 = qtile * 64;
    const float inv_d = 1.0f / (float)D_;

    const size_t row_base = (size_t)b * T_;
    const int hcol = h * D_;

#pragma unroll
    for (int it = 0; it < 4; it++) {
        int idx = it * 256 + tid;
        int q = idx >> 4;
        int d4 = (idx & 15) * 4;
        float4 qv = *reinterpret_cast<const float4*>(
            qkv + (row_base + q0 + q) * C3_ + hcol + d4);
        Qst[(d4 + 0) * 64 + q] = qv.x;
        Qst[(d4 + 1) * 64 + q] = qv.y;
        Qst[(d4 + 2) * 64 + q] = qv.z;
        Qst[(d4 + 3) * 64 + q] = qv.w;
    }
    if (tid < 64) {
        m_s[tid] = -INFINITY;
        l_s[tid] = 0.0f;
    }

    float o[4][4];
#pragma unroll
    for (int i = 0; i < 4; i++)
#pragma unroll
        for (int j = 0; j < 4; j++) o[i][j] = 0.0f;

    const int ntiles = qtile + 1;
    for (int kt = 0; kt < ntiles; kt++) {
        const int k0 = kt * 64;
        __syncthreads();

#pragma unroll
        for (int it = 0; it < 4; it++) {
            int idx = it * 256 + tid;
            int kk = idx >> 4;
            int d4 = (idx & 15) * 4;
            const float* rowp = qkv + (row_base + k0 + kk) * C3_;
            float4 kv = *reinterpret_cast<const float4*>(rowp + C_ + hcol + d4);
            Kst[(d4 + 0) * 64 + kk] = kv.x;
            Kst[(d4 + 1) * 64 + kk] = kv.y;
            Kst[(d4 + 2) * 64 + kk] = kv.z;
            Kst[(d4 + 3) * 64 + kk] = kv.w;
            float4 vv = *reinterpret_cast<const float4*>(rowp + 2 * C_ + hcol + d4);
            *reinterpret_cast<float4*>(&Vs[kk * 64 + d4]) = vv;
        }
        __syncthreads();

        float acc[4][4];
#pragma unroll
        for (int i = 0; i < 4; i++)
#pragma unroll
            for (int j = 0; j < 4; j++) acc[i][j] = 0.0f;

#pragma unroll 8
        for (int d = 0; d < 64; d++) {
            float a[4], bb[4];
            *reinterpret_cast<float4*>(a)  = *reinterpret_cast<float4*>(&Qst[d * 64 + ty * 4]);
            *reinterpret_cast<float4*>(bb) = *reinterpret_cast<float4*>(&Kst[d * 64 + tx * 4]);
#pragma unroll
            for (int i = 0; i < 4; i++)
#pragma unroll
                for (int j = 0; j < 4; j++)
                    acc[i][j] = fmaf(a[i], bb[j], acc[i][j]);
        }

        const bool diag = (kt == qtile);
#pragma unroll
        for (int i = 0; i < 4; i++) {
            int qr = ty * 4 + i;
#pragma unroll
            for (int j = 0; j < 4; j++) {
                int kc = tx * 4 + j;
                float s = acc[i][j] * inv_d;
                if (diag && kc > qr) s = -1e30f;
                Ssm[qr * SSM_LD + kc] = s;
            }
        }
        __syncthreads();

        if (tid < 64) {
            const int r = tid;
            float mo = m_s[r];
            float mn = mo;
#pragma unroll 8
            for (int j = 0; j < 64; j++)
                mn = fmaxf(mn, Ssm[r * SSM_LD + j]);
            float corr = __expf(mo - mn);
            float sum = 0.0f;
#pragma unroll 8
            for (int j = 0; j < 64; j++) {
                float p = __expf(Ssm[r * SSM_LD + j] - mn);
                Ssm[r * SSM_LD + j] = p;
                sum += p;
            }
            l_s[r] = l_s[r] * corr + sum;
            m_s[r] = mn;
            sc_s[r] = corr;
        }
        __syncthreads();

        float ci[4];
#pragma unroll
        for (int i = 0; i < 4; i++) ci[i] = sc_s[ty * 4 + i];
#pragma unroll
        for (int i = 0; i < 4; i++)
#pragma unroll
            for (int j = 0; j < 4; j++) o[i][j] *= ci[i];

#pragma unroll 4
        for (int k = 0; k < 64; k++) {
            float p[4], v[4];
#pragma unroll
            for (int i = 0; i < 4; i++) p[i] = Ssm[(ty * 4 + i) * SSM_LD + k];
            *reinterpret_cast<float4*>(v) = *reinterpret_cast<float4*>(&Vs[k * 64 + tx * 4]);
#pragma unroll
            for (int i = 0; i < 4; i++)
#pragma unroll
                for (int j = 0; j < 4; j++)
                    o[i][j] = fmaf(p[i], v[j], o[i][j]);
        }
    }
    __syncthreads();

#pragma unroll
    for (int i = 0; i < 4; i++) {
        int qr = ty * 4 + i;
        float invl = 1.0f / l_s[qr];
        float* yrow = y + (row_base + q0 + qr) * C_ + hcol + tx * 4;
        float4 ov = make_float4(o[i][0] * invl, o[i][1] * invl,
                                o[i][2] * invl, o[i][3] * invl);
        *reinterpret_cast<float4*>(yrow) = ov;
    }
}

// ---------------------------------------------------------------------------
// Launch
// ---------------------------------------------------------------------------
extern "C" void kernel_launch(void* const* d_in, const int* in_sizes, int n_in,
                              void* d_out, int out_size) {
    const float* x      = (const float*)d_in[0];   // [4,2048,1024]
    const float* W_attn = (const float*)d_in[1];   // [1024,3072]
    const float* W_proj = (const float*)d_in[2];   // [1024,1024]
    float* out = (float*)d_out;

    float* qkv;
    float* y;
    cudaGetSymbolAddress((void**)&qkv, g_qkv);
    cudaGetSymbolAddress((void**)&y, g_y);

    cudaFuncSetAttribute(gemm_tf32_kernel,
                         cudaFuncAttributeMaxDynamicSharedMemorySize, GSMEM_BYTES);
    cudaFuncSetAttribute(attn_kernel,
                         cudaFuncAttributeMaxDynamicSharedMemorySize, ATTN_SMEM_BYTES);

    // 1) qkv = x @ W_attn   (tf32 tensor cores)
    gemm_tf32_kernel<<<dim3(C3_ / BN, M_ / BM), 128, GSMEM_BYTES>>>(
        x, W_attn, qkv, M_, C3_, C_);

    // 2) causal attention -> y (fp32)
    attn_kernel<<<dim3(T_ / 64, H_, B_), 256, ATTN_SMEM_BYTES>>>(qkv, y);

    // 3) out = y @ W_proj   (tf32 tensor cores)
    gemm_tf32_kernel<<<dim3(C_ / BN, M_ / BM), 128, GSMEM_BYTES>>>(
        y, W_proj, out, M_, C_, C_);
}

// round 4
// speedup vs baseline: 3.5858x; 2.2095x over previous
#include <cuda_runtime.h>
#include <cuda_bf16.h>
#include <math.h>

// Problem constants
#define B_   4
#define T_   2048
#define C_   1024
#define H_   16
#define D_   64
#define M_   (B_ * T_)        // 8192
#define C3_  (3 * C_)         // 3072

// ---------------------------------------------------------------------------
// Device scratch (no cudaMalloc allowed)
// ---------------------------------------------------------------------------
__device__ __align__(1024) float g_qkv[M_ * C3_];   // [8192,3072]
__device__ __align__(1024) float g_y[M_ * C_];      // [8192,1024]

// ---------------------------------------------------------------------------
// Helpers
// ---------------------------------------------------------------------------
__device__ __forceinline__ unsigned smem_to_u32(const void* p) {
    unsigned a;
    asm("{ .reg .u64 t; cvta.to.shared.u64 t, %1; cvt.u32.u64 %0, t; }"
        : "=r"(a) : "l"(p));
    return a;
}

#define CP_ASYNC16(dst, src) \
    asm volatile("cp.async.cg.shared.global [%0], [%1], 16;" \
                 :: "r"(dst), "l"(src) : "memory")

__device__ __forceinline__ unsigned f2tf32(float x) {
    unsigned r;
    asm("cvt.rna.tf32.f32 %0, %1;" : "=r"(r) : "f"(x));
    return r;
}

__device__ __forceinline__ float f2tf32f(float x) {
    return __uint_as_float(f2tf32(x));
}

__device__ __forceinline__ void mma_tf32(float* c, const unsigned* a,
                                         const unsigned* b) {
    asm volatile(
        "mma.sync.aligned.m16n8k8.row.col.f32.tf32.tf32.f32 "
        "{%0,%1,%2,%3}, {%4,%5,%6,%7}, {%8,%9}, {%0,%1,%2,%3};"
        : "+f"(c[0]), "+f"(c[1]), "+f"(c[2]), "+f"(c[3])
        : "r"(a[0]), "r"(a[1]), "r"(a[2]), "r"(a[3]),
          "r"(b[0]), "r"(b[1]));
}

// ---------------------------------------------------------------------------
// tf32 tensor-core GEMM (unchanged from R3): C[M,N] = A[M,K]*B[K,N]
// ---------------------------------------------------------------------------
#define BM 128
#define BN 128
#define BK 32
#define GSTAGES 3
#define A_LDW 36
#define B_LDW 136
#define A_STAGE_W (BM * A_LDW)
#define B_STAGE_W (BK * B_LDW)
#define STAGE_W   (A_STAGE_W + B_STAGE_W)
#define GSMEM_BYTES (GSTAGES * STAGE_W * 4)

__global__ void __launch_bounds__(128, 2)
gemm_tf32_kernel(const float* __restrict__ A, const float* __restrict__ Bm,
                 float* __restrict__ Cm, int M, int N, int K) {
    extern __shared__ __align__(16) float sm[];
    const unsigned sbase = smem_to_u32(sm);

    const int tid = threadIdx.x;
    const int wid = tid >> 5;
    const int lane = tid & 31;
    const int g = lane >> 2;
    const int t = lane & 3;
    const int warp_m = wid & 1;
    const int warp_n = wid >> 1;
    const int m0 = blockIdx.y * BM;
    const int n0 = blockIdx.x * BN;
    const int nchunks = K / BK;

    float acc[4][8][4];
#pragma unroll
    for (int i = 0; i < 4; i++)
#pragma unroll
        for (int j = 0; j < 8; j++)
#pragma unroll
            for (int r = 0; r < 4; r++) acc[i][j][r] = 0.0f;

    auto issue = [&](int chunk) {
        const unsigned st = sbase + (unsigned)((chunk % GSTAGES) * STAGE_W * 4);
#pragma unroll
        for (int i = 0; i < 8; i++) {
            int idx = tid + i * 128;
            int row = idx >> 3;
            int c4 = (idx & 7) * 4;
            const float* src = A + (size_t)(m0 + row) * K + chunk * BK + c4;
            unsigned dst = st + (unsigned)((row * A_LDW + c4) * 4);
            CP_ASYNC16(dst, src);
        }
        const unsigned stb = st + (unsigned)(A_STAGE_W * 4);
#pragma unroll
        for (int i = 0; i < 8; i++) {
            int idx = tid + i * 128;
            int kr = idx >> 5;
            int c4 = (idx & 31) * 4;
            const float* src = Bm + (size_t)(chunk * BK + kr) * N + n0 + c4;
            unsigned dst = stb + (unsigned)((kr * B_LDW + c4) * 4);
            CP_ASYNC16(dst, src);
        }
        asm volatile("cp.async.commit_group;" ::: "memory");
    };

    issue(0);
    issue(1);

    for (int c = 0; c < nchunks; c++) {
        if (c < nchunks - 1)
            asm volatile("cp.async.wait_group 1;" ::: "memory");
        else
            asm volatile("cp.async.wait_group 0;" ::: "memory");
        __syncthreads();

        if (c + 2 < nchunks) issue(c + 2);

        const float* As = sm + (c % GSTAGES) * STAGE_W + warp_m * 64 * A_LDW;
        const float* Bs = sm + (c % GSTAGES) * STAGE_W + A_STAGE_W + warp_n * 64;

#pragma unroll
        for (int ks = 0; ks < 4; ks++) {
            unsigned af[4][4], bf[8][2];
#pragma unroll
            for (int mt = 0; mt < 4; mt++) {
                const float* ap = As + (mt * 16 + g) * A_LDW + ks * 8 + t;
                af[mt][0] = f2tf32(ap[0]);
                af[mt][1] = f2tf32(ap[8 * A_LDW]);
                af[mt][2] = f2tf32(ap[4]);
                af[mt][3] = f2tf32(ap[8 * A_LDW + 4]);
            }
#pragma unroll
            for (int nt = 0; nt < 8; nt++) {
                const float* bp = Bs + (ks * 8 + t) * B_LDW + nt * 8 + g;
                bf[nt][0] = f2tf32(bp[0]);
                bf[nt][1] = f2tf32(bp[4 * B_LDW]);
            }
#pragma unroll
            for (int mt = 0; mt < 4; mt++)
#pragma unroll
                for (int nt = 0; nt < 8; nt++)
                    mma_tf32(acc[mt][nt], af[mt], bf[nt]);
        }
    }

#pragma unroll
    for (int mt = 0; mt < 4; mt++) {
        int row0 = m0 + warp_m * 64 + mt * 16 + g;
#pragma unroll
        for (int nt = 0; nt < 8; nt++) {
            int col = n0 + warp_n * 64 + nt * 8 + 2 * t;
            float2 v0 = make_float2(acc[mt][nt][0], acc[mt][nt][1]);
            float2 v1 = make_float2(acc[mt][nt][2], acc[mt][nt][3]);
            *reinterpret_cast<float2*>(Cm + (size_t)row0 * N + col) = v0;
            *reinterpret_cast<float2*>(Cm + (size_t)(row0 + 8) * N + col) = v1;
        }
    }
}

// ---------------------------------------------------------------------------
// Tensor-core flash attention (tf32 mma, fp32 softmax, causal, 1/D folded
// into Q). CTA: 128 q-rows for one (b,h). 128 threads = 4 warps; each warp
// owns 32 q-rows. Key tiles of 64.
// smem: Qs[128][68], Ks[64][68], Vs[64][72], Ps[4][32][68] — all tf32-rounded.
// ---------------------------------------------------------------------------
#define QK_LD 68
#define V_LD  72
#define ATTN_Q_W   (128 * QK_LD)
#define ATTN_K_W   (64 * QK_LD)
#define ATTN_V_W   (64 * V_LD)
#define ATTN_P_W   (4 * 32 * QK_LD)
#define ATTN2_SMEM_BYTES ((ATTN_Q_W + ATTN_K_W + ATTN_V_W + ATTN_P_W) * 4)

__global__ void __launch_bounds__(128, 2)
attn_tc_kernel(const float* __restrict__ qkv, float* __restrict__ y) {
    extern __shared__ __align__(16) float sm[];
    float* Qs = sm;                        // [128][68]
    float* Ks = Qs + ATTN_Q_W;             // [64][68]
    float* Vs = Ks + ATTN_K_W;             // [64][72]
    float* Ps = Vs + ATTN_V_W;             // [4][32][68]

    const int tid = threadIdx.x;
    const int wid = tid >> 5;
    const int lane = tid & 31;
    const int g = lane >> 2;   // A-row / B-col index
    const int t = lane & 3;    // A-col / B-row index
    const int qi = (gridDim.x - 1) - blockIdx.x;   // heavy tiles first
    const int h = blockIdx.y;
    const int b = blockIdx.z;
    const int q0 = qi * 128;
    const size_t row_base = (size_t)b * T_;
    const int hcol = h * D_;
    const float inv_d = 1.0f / (float)D_;

    float* Psw = Ps + wid * 32 * QK_LD;

    // ---- Load Q tile (scaled by 1/D, tf32-rounded) ----
#pragma unroll
    for (int i = 0; i < 16; i++) {
        int idx = i * 128 + tid;           // 0..2047 float4
        int r = idx >> 4;
        int c4 = (idx & 15) * 4;
        float4 v = *reinterpret_cast<const float4*>(
            qkv + (row_base + q0 + r) * C3_ + hcol + c4);
        float4 w = make_float4(f2tf32f(v.x * inv_d), f2tf32f(v.y * inv_d),
                               f2tf32f(v.z * inv_d), f2tf32f(v.w * inv_d));
        *reinterpret_cast<float4*>(&Qs[r * QK_LD + c4]) = w;
    }

    // Per-thread softmax state: rows (mt*16+g) and (mt*16+g+8)
    float mst[2][2], lst[2][2];
#pragma unroll
    for (int mt = 0; mt < 2; mt++) {
        mst[mt][0] = -1e30f; mst[mt][1] = -1e30f;
        lst[mt][0] = 0.0f;   lst[mt][1] = 0.0f;
    }
    float o[2][8][4];
#pragma unroll
    for (int mt = 0; mt < 2; mt++)
#pragma unroll
        for (int nt = 0; nt < 8; nt++)
#pragma unroll
            for (int r = 0; r < 4; r++) o[mt][nt][r] = 0.0f;

    const int nkt = 2 * qi + 2;
    for (int kt = 0; kt < nkt; kt++) {
        const int k0 = kt * 64;
        __syncthreads();

        // ---- Fill K and V tiles (tf32-rounded) ----
#pragma unroll
        for (int i = 0; i < 8; i++) {
            int idx = i * 128 + tid;       // 0..1023 float4
            int r = idx >> 4;
            int c4 = (idx & 15) * 4;
            const float* rp = qkv + (row_base + k0 + r) * C3_ + hcol;
            float4 kv = *reinterpret_cast<const float4*>(rp + C_ + c4);
            float4 kw = make_float4(f2tf32f(kv.x), f2tf32f(kv.y),
                                    f2tf32f(kv.z), f2tf32f(kv.w));
            *reinterpret_cast<float4*>(&Ks[r * QK_LD + c4]) = kw;
            float4 vv = *reinterpret_cast<const float4*>(rp + 2 * C_ + c4);
            float4 vw = make_float4(f2tf32f(vv.x), f2tf32f(vv.y),
                                    f2tf32f(vv.z), f2tf32f(vv.w));
            *reinterpret_cast<float4*>(&Vs[r * V_LD + c4]) = vw;
        }
        __syncthreads();

        // ---- S = Q K^T ----
        float sf[2][8][4];
#pragma unroll
        for (int mt = 0; mt < 2; mt++)
#pragma unroll
            for (int nt = 0; nt < 8; nt++)
#pragma unroll
                for (int r = 0; r < 4; r++) sf[mt][nt][r] = 0.0f;

#pragma unroll
        for (int ks = 0; ks < 8; ks++) {
            unsigned a[2][4];
#pragma unroll
            for (int mt = 0; mt < 2; mt++) {
                const float* ap = Qs + (wid * 32 + mt * 16 + g) * QK_LD + ks * 8 + t;
                a[mt][0] = __float_as_uint(ap[0]);
                a[mt][1] = __float_as_uint(ap[8 * QK_LD]);
                a[mt][2] = __float_as_uint(ap[4]);
                a[mt][3] = __float_as_uint(ap[8 * QK_LD + 4]);
            }
#pragma unroll
            for (int nt = 0; nt < 8; nt++) {
                unsigned bb[2];
                const float* bp = Ks + (nt * 8 + g) * QK_LD + ks * 8 + t;
                bb[0] = __float_as_uint(bp[0]);
                bb[1] = __float_as_uint(bp[4]);
                mma_tf32(sf[0][nt], a[0], bb);
                mma_tf32(sf[1][nt], a[1], bb);
            }
        }

        // ---- Masked online softmax (registers) ----
        const bool need_mask = (kt >= 2 * qi);
#pragma unroll
        for (int mt = 0; mt < 2; mt++) {
            const int qr0 = q0 + wid * 32 + mt * 16 + g;
            const int qr1 = qr0 + 8;
            float rmax0 = -1e30f, rmax1 = -1e30f;
#pragma unroll
            for (int nt = 0; nt < 8; nt++) {
                if (need_mask) {
                    int kc = k0 + nt * 8 + 2 * t;
                    if (kc > qr0)     sf[mt][nt][0] = -1e30f;
                    if (kc + 1 > qr0) sf[mt][nt][1] = -1e30f;
                    if (kc > qr1)     sf[mt][nt][2] = -1e30f;
                    if (kc + 1 > qr1) sf[mt][nt][3] = -1e30f;
                }
                rmax0 = fmaxf(rmax0, fmaxf(sf[mt][nt][0], sf[mt][nt][1]));
                rmax1 = fmaxf(rmax1, fmaxf(sf[mt][nt][2], sf[mt][nt][3]));
            }
            rmax0 = fmaxf(rmax0, __shfl_xor_sync(0xffffffffu, rmax0, 1));
            rmax0 = fmaxf(rmax0, __shfl_xor_sync(0xffffffffu, rmax0, 2));
            rmax1 = fmaxf(rmax1, __shfl_xor_sync(0xffffffffu, rmax1, 1));
            rmax1 = fmaxf(rmax1, __shfl_xor_sync(0xffffffffu, rmax1, 2));

            const float mn0 = fmaxf(mst[mt][0], rmax0);
            const float mn1 = fmaxf(mst[mt][1], rmax1);
            const float corr0 = __expf(mst[mt][0] - mn0);
            const float corr1 = __expf(mst[mt][1] - mn1);
            float sum0 = 0.0f, sum1 = 0.0f;
#pragma unroll
            for (int nt = 0; nt < 8; nt++) {
                float p0 = __expf(sf[mt][nt][0] - mn0);
                float p1 = __expf(sf[mt][nt][1] - mn0);
                float p2 = __expf(sf[mt][nt][2] - mn1);
                float p3 = __expf(sf[mt][nt][3] - mn1);
                sum0 += p0 + p1;
                sum1 += p2 + p3;
                float* pr0 = Psw + (mt * 16 + g) * QK_LD + nt * 8 + 2 * t;
                float* pr1 = Psw + (mt * 16 + g + 8) * QK_LD + nt * 8 + 2 * t;
                *reinterpret_cast<float2*>(pr0) =
                    make_float2(f2tf32f(p0), f2tf32f(p1));
                *reinterpret_cast<float2*>(pr1) =
                    make_float2(f2tf32f(p2), f2tf32f(p3));
            }
            sum0 += __shfl_xor_sync(0xffffffffu, sum0, 1);
            sum0 += __shfl_xor_sync(0xffffffffu, sum0, 2);
            sum1 += __shfl_xor_sync(0xffffffffu, sum1, 1);
            sum1 += __shfl_xor_sync(0xffffffffu, sum1, 2);

            lst[mt][0] = lst[mt][0] * corr0 + sum0;
            lst[mt][1] = lst[mt][1] * corr1 + sum1;
            mst[mt][0] = mn0;
            mst[mt][1] = mn1;
#pragma unroll
            for (int nt = 0; nt < 8; nt++) {
                o[mt][nt][0] *= corr0;
                o[mt][nt][1] *= corr0;
                o[mt][nt][2] *= corr1;
                o[mt][nt][3] *= corr1;
            }
        }
        __syncwarp();

        // ---- O += P V ----
#pragma unroll
        for (int ks = 0; ks < 8; ks++) {
            unsigned a[2][4];
#pragma unroll
            for (int mt = 0; mt < 2; mt++) {
                const float* ap = Psw + (mt * 16 + g) * QK_LD + ks * 8 + t;
                a[mt][0] = __float_as_uint(ap[0]);
                a[mt][1] = __float_as_uint(ap[8 * QK_LD]);
                a[mt][2] = __float_as_uint(ap[4]);
                a[mt][3] = __float_as_uint(ap[8 * QK_LD + 4]);
            }
#pragma unroll
            for (int nt = 0; nt < 8; nt++) {
                unsigned bb[2];
                const float* bp = Vs + (ks * 8 + t) * V_LD + nt * 8 + g;
                bb[0] = __float_as_uint(bp[0]);
                bb[1] = __float_as_uint(bp[4 * V_LD]);
                mma_tf32(o[0][nt], a[0], bb);
                mma_tf32(o[1][nt], a[1], bb);
            }
        }
    }

    // ---- Epilogue: normalize and store ----
#pragma unroll
    for (int mt = 0; mt < 2; mt++) {
        const float il0 = 1.0f / lst[mt][0];
        const float il1 = 1.0f / lst[mt][1];
        const size_t r0 = row_base + q0 + wid * 32 + mt * 16 + g;
#pragma unroll
        for (int nt = 0; nt < 8; nt++) {
            const int col = hcol + nt * 8 + 2 * t;
            *reinterpret_cast<float2*>(y + r0 * C_ + col) =
                make_float2(o[mt][nt][0] * il0, o[mt][nt][1] * il0);
            *reinterpret_cast<float2*>(y + (r0 + 8) * C_ + col) =
                make_float2(o[mt][nt][2] * il1, o[mt][nt][3] * il1);
        }
    }
}

// ---------------------------------------------------------------------------
// Launch
// ---------------------------------------------------------------------------
extern "C" void kernel_launch(void* const* d_in, const int* in_sizes, int n_in,
                              void* d_out, int out_size) {
    const float* x      = (const float*)d_in[0];   // [4,2048,1024]
    const float* W_attn = (const float*)d_in[1];   // [1024,3072]
    const float* W_proj = (const float*)d_in[2];   // [1024,1024]
    float* out = (float*)d_out;

    float* qkv;
    float* y;
    cudaGetSymbolAddress((void**)&qkv, g_qkv);
    cudaGetSymbolAddress((void**)&y, g_y);

    cudaFuncSetAttribute(gemm_tf32_kernel,
                         cudaFuncAttributeMaxDynamicSharedMemorySize, GSMEM_BYTES);
    cudaFuncSetAttribute(attn_tc_kernel,
                         cudaFuncAttributeMaxDynamicSharedMemorySize, ATTN2_SMEM_BYTES);

    // 1) qkv = x @ W_attn   (tf32 tensor cores)
    gemm_tf32_kernel<<<dim3(C3_ / BN, M_ / BM), 128, GSMEM_BYTES>>>(
        x, W_attn, qkv, M_, C3_, C_);

    // 2) causal attention -> y (tf32 tensor cores)
    attn_tc_kernel<<<dim3(T_ / 128, H_, B_), 128, ATTN2_SMEM_BYTES>>>(qkv, y);

    // 3) out = y @ W_proj   (tf32 tensor cores)
    gemm_tf32_kernel<<<dim3(C_ / BN, M_ / BM), 128, GSMEM_BYTES>>>(
        y, W_proj, out, M_, C_, C_);
}